// round 3
// baseline (speedup 1.0000x reference)
#include <cuda_runtime.h>
#include <math.h>

// ---------------- problem constants ----------------
#define NTOT   22743
#define N0     1083
#define N1     4332
#define N2     17328
#define OFF1   1083
#define OFF2   5415
#define BATCH  8
#define TOPK   1000
#define NCAND  3000
#define MAXDET 100
#define IMGMAX 607
#define SORTN  4096
#define CH     512          // NMS chunk size
#define CW     16           // CH/32

// ---------------- device scratch ----------------
__device__ float g_score[BATCH * NTOT];
__device__ int   g_cls[BATCH * NTOT];
__device__ float g_cscore[BATCH * NCAND];
__device__ int   g_cidx[BATCH * NCAND];     // anchor index n within image

__device__ __forceinline__ float sigm(float x) { return 1.0f / (1.0f + expf(-x)); }

// ---------------- stage 1: decode scores only (4 threads / anchor) ----------------
__global__ void decode_kernel(
    const float* __restrict__ obj0, const float* __restrict__ cls0,
    const float* __restrict__ obj1, const float* __restrict__ cls1,
    const float* __restrict__ obj2, const float* __restrict__ cls2)
{
    int t = blockIdx.x * blockDim.x + threadIdx.x;
    int a = t >> 2;
    int sub = t & 3;
    if (a >= BATCH * NTOT) a = BATCH * NTOT - 1;   // duplicates write identical data
    int b = a / NTOT;
    int n = a - b * NTOT;

    const float *obj, *cls;
    int local, cnt;
    if (n < N0)        { obj = obj0; cls = cls0; local = n;        cnt = N0; }
    else if (n < OFF2) { obj = obj1; cls = cls1; local = n - OFF1; cnt = N1; }
    else               { obj = obj2; cls = cls2; local = n - OFF2; cnt = N2; }

    size_t base = (size_t)b * cnt + local;

    // each of 4 threads reduces 20 classes (5 float4)
    const float4* cp4 = reinterpret_cast<const float4*>(cls + base * 80) + sub * 5;
    float4 v0 = __ldg(cp4);
    float4 v1 = __ldg(cp4 + 1);
    float4 v2 = __ldg(cp4 + 2);
    float4 v3 = __ldg(cp4 + 3);
    float4 v4 = __ldg(cp4 + 4);

    float best = v0.x; int bi = 0;
    if (v0.y > best) { best = v0.y; bi = 1; }
    if (v0.z > best) { best = v0.z; bi = 2; }
    if (v0.w > best) { best = v0.w; bi = 3; }
    if (v1.x > best) { best = v1.x; bi = 4; }
    if (v1.y > best) { best = v1.y; bi = 5; }
    if (v1.z > best) { best = v1.z; bi = 6; }
    if (v1.w > best) { best = v1.w; bi = 7; }
    if (v2.x > best) { best = v2.x; bi = 8; }
    if (v2.y > best) { best = v2.y; bi = 9; }
    if (v2.z > best) { best = v2.z; bi = 10; }
    if (v2.w > best) { best = v2.w; bi = 11; }
    if (v3.x > best) { best = v3.x; bi = 12; }
    if (v3.y > best) { best = v3.y; bi = 13; }
    if (v3.z > best) { best = v3.z; bi = 14; }
    if (v3.w > best) { best = v3.w; bi = 15; }
    if (v4.x > best) { best = v4.x; bi = 16; }
    if (v4.y > best) { best = v4.y; bi = 17; }
    if (v4.z > best) { best = v4.z; bi = 18; }
    if (v4.w > best) { best = v4.w; bi = 19; }
    bi += sub * 20;

    // combine across the 4 sub-lanes; tie -> lower class index (first occurrence)
#pragma unroll
    for (int off = 1; off <= 2; off <<= 1) {
        float ov = __shfl_xor_sync(0xffffffffu, best, off);
        int   oi = __shfl_xor_sync(0xffffffffu, bi, off);
        if (ov > best || (ov == best && oi < bi)) { best = ov; bi = oi; }
    }

    if (sub == 0) {
        float o = sigm(__ldg(obj + base));
        g_score[a] = sigm(best) * o;
        g_cls[a]   = bi;
    }
}

// ---------------- stage 2: register-cached exact top-1000 ----------------
#define TKT 512
#define PER 34   // ceil(17328/512)

__global__ void __launch_bounds__(TKT) topk_kernel()
{
    int level = blockIdx.x, b = blockIdx.y;
    int offs = (level == 0) ? 0  : ((level == 1) ? OFF1 : OFF2);
    int cnt  = (level == 0) ? N0 : ((level == 1) ? N1  : N2);
    const unsigned* sc = reinterpret_cast<const unsigned*>(g_score + b * NTOT + offs);

    int tid = threadIdx.x;
    int lane = tid & 31, warp = tid >> 5;

    unsigned v[PER];
#pragma unroll
    for (int k = 0; k < PER; ++k) {
        int i = tid + (k << 9);
        v[k] = (i < cnt) ? __ldg(sc + i) : 0u;
    }

    __shared__ unsigned wred[16];
    __shared__ unsigned sb[2];
    __shared__ int s_found;
    if (tid == 0) { sb[0] = 0u; sb[1] = 0x3F800000u; }
    __syncthreads();

    unsigned lo = 0u, hi = 0x3F800000u;
    while (lo < hi) {
        unsigned mid = lo + ((hi - lo) >> 1);
        unsigned c = 0;
#pragma unroll
        for (int k = 0; k < PER; ++k) c += (v[k] > mid) ? 1u : 0u;
#pragma unroll
        for (int o = 16; o; o >>= 1) c += __shfl_down_sync(0xffffffffu, c, o);
        if (lane == 0) wred[warp] = c;
        __syncthreads();
        if (tid < 32) {
            unsigned s = (tid < 16) ? wred[tid] : 0u;
#pragma unroll
            for (int o = 8; o; o >>= 1) s += __shfl_down_sync(0xffffffffu, s, o);
            if (tid == 0) { if (s < (unsigned)TOPK) sb[1] = mid; else sb[0] = mid + 1u; }
        }
        __syncthreads();
        lo = sb[0]; hi = sb[1];
        __syncthreads();
    }
    unsigned tau = lo;

    unsigned c = 0;
#pragma unroll
    for (int k = 0; k < PER; ++k) c += (v[k] > tau) ? 1u : 0u;
    unsigned ws = c;
#pragma unroll
    for (int o = 1; o < 32; o <<= 1) {
        unsigned nb = __shfl_up_sync(0xffffffffu, ws, o);
        if (lane >= o) ws += nb;
    }
    if (lane == 31) wred[warp] = ws;
    __syncthreads();
    if (tid < 32) {
        unsigned s = (tid < 16) ? wred[tid] : 0u;
#pragma unroll
        for (int o = 1; o < 16; o <<= 1) {
            unsigned nb = __shfl_up_sync(0xffffffffu, s, o);
            if (lane >= o) s += nb;
        }
        if (tid < 16) wred[tid] = s;
    }
    __syncthreads();
    unsigned excl = ws - c + (warp ? wred[warp - 1] : 0u);
    unsigned mtot = wred[15];

    unsigned pos = excl;
#pragma unroll
    for (int k = 0; k < PER; ++k) {
        int i = tid + (k << 9);
        if (i < cnt && v[k] > tau) {
            int s = b * NCAND + level * TOPK + (int)pos;
            g_cscore[s] = __uint_as_float(v[k]);
            g_cidx[s]   = offs + i;
            pos++;
        }
    }
    __syncthreads();

    int r = TOPK - (int)mtot;
    int last = -1;
    for (int rep = 0; rep < r; ++rep) {
        unsigned lm = 0xFFFFFFFFu;
#pragma unroll
        for (int k = 0; k < PER; ++k) {
            int i = tid + (k << 9);
            if (i < cnt && i > last && v[k] == tau) lm = min(lm, (unsigned)i);
        }
#pragma unroll
        for (int o = 16; o; o >>= 1) lm = min(lm, __shfl_down_sync(0xffffffffu, lm, o));
        if (lane == 0) wred[warp] = lm;
        __syncthreads();
        if (tid < 32) {
            unsigned s = (tid < 16) ? wred[tid] : 0xFFFFFFFFu;
#pragma unroll
            for (int o = 8; o; o >>= 1) s = min(s, __shfl_down_sync(0xffffffffu, s, o));
            if (tid == 0) s_found = (int)s;
        }
        __syncthreads();
        int found = s_found;
        if (tid == 0 && found >= 0 && found < cnt) {
            int s = b * NCAND + level * TOPK + (int)mtot + rep;
            g_cscore[s] = __uint_as_float(tau);
            g_cidx[s]   = offs + found;
        }
        last = found;
        __syncthreads();
    }
}

// ---------------- stage 3: fused bitonic sort + chunked bitmask NMS ----------------
__device__ __forceinline__ unsigned long long u64max(unsigned long long a, unsigned long long b) { return a > b ? a : b; }
__device__ __forceinline__ unsigned long long u64min(unsigned long long a, unsigned long long b) { return a < b ? a : b; }
__device__ __forceinline__ void cswap(unsigned long long& a, unsigned long long& b, bool desc)
{
    if (desc ? (a < b) : (a > b)) { unsigned long long t = a; a = b; b = t; }
}

__global__ void __launch_bounds__(1024) sortnms_kernel(
    const float* __restrict__ reg0, const float* __restrict__ anc0,
    const float* __restrict__ reg1, const float* __restrict__ anc1,
    const float* __restrict__ reg2, const float* __restrict__ anc2,
    float* __restrict__ out)
{
    int b = blockIdx.x;
    int tid = threadIdx.x;
    int i0 = tid << 2;

    __shared__ union ShMem {
        unsigned long long sk[SORTN];     // sort workspace
        unsigned M[CH][CW];               // NMS suppression matrix (reuses same bytes)
    } sh;
    __shared__ unsigned long long ckey[CH];
    __shared__ int cx1[CH], cy1[CH], cx2[CH], cy2[CH], cslot[CH];
    __shared__ unsigned supv[CW];
    __shared__ unsigned limw[CW];
    __shared__ int kp1[MAXDET], kp2[MAXDET], kslot[MAXDET];
    __shared__ int s_kept, s_done;
    __shared__ int s_limit;

    if (tid == 0) { s_kept = 0; s_done = 0; }

    // ---- build keys: score bits << 32 | ~slot (desc score, asc slot on ties) ----
    const float* cs = g_cscore + b * NCAND;
    unsigned long long r[4];
#pragma unroll
    for (int s = 0; s < 4; ++s) {
        int i = i0 + s;
        r[s] = (i < NCAND)
             ? (((unsigned long long)__float_as_uint(__ldg(cs + i)) << 32)
                | (unsigned long long)(0xFFFFFFFFu - (unsigned)i))
             : 0ull;
    }
    __syncthreads();

    // ---- bitonic sort (descending), 4 elems/thread ----
    for (int k = 2; k <= SORTN; k <<= 1) {
        for (int j = k >> 1; j > 0; j >>= 1) {
            if (j >= 128) {
                sh.sk[i0] = r[0]; sh.sk[i0 + 1] = r[1]; sh.sk[i0 + 2] = r[2]; sh.sk[i0 + 3] = r[3];
                __syncthreads();
                int pb = i0 ^ j;
                bool takeMax = (((i0 & k) == 0) != ((i0 & j) != 0));
#pragma unroll
                for (int s = 0; s < 4; ++s) {
                    unsigned long long p = sh.sk[pb + s];
                    r[s] = takeMax ? u64max(r[s], p) : u64min(r[s], p);
                }
                __syncthreads();
            } else if (j >= 4) {
                int lx = j >> 2;
                bool takeMax = (((i0 & k) == 0) != ((i0 & j) != 0));
#pragma unroll
                for (int s = 0; s < 4; ++s) {
                    unsigned long long p = __shfl_xor_sync(0xffffffffu, r[s], lx);
                    r[s] = takeMax ? u64max(r[s], p) : u64min(r[s], p);
                }
            } else if (j == 2) {
                cswap(r[0], r[2], ((i0    ) & k) == 0);
                cswap(r[1], r[3], ((i0 + 2) & k) == 0 ? false : false);  // placeholder, fixed below
                cswap(r[1], r[3], ((i0 + 1) & k) == 0);
            } else {
                cswap(r[0], r[1], ((i0    ) & k) == 0);
                cswap(r[2], r[3], ((i0 + 2) & k) == 0);
            }
        }
    }
    // (note: the duplicated j==2 cswap(r[1],r[3],false) above is a no-op guard; the
    //  real exchange is the following line with the correct direction bit)

    const int* cidx = g_cidx + b * NCAND;

    // ---- chunked NMS ----
    for (int cb = 0; cb < NCAND; cb += CH) {
        // stage this chunk's sorted keys from registers into smem
#pragma unroll
        for (int s = 0; s < 4; ++s) {
            int rank = i0 + s;
            if (rank >= cb && rank < cb + CH) ckey[rank - cb] = r[s];
        }
        __syncthreads();

        // load + lazily decode boxes for valid candidates
        bool valid = false;
        if (tid < CH) {
            unsigned long long key = ckey[tid];
            float sc = __uint_as_float((unsigned)(key >> 32));
            unsigned slot = 0xFFFFFFFFu - (unsigned)key;
            valid = (sc > 0.05f);
            if (valid) {
                int n = __ldg(cidx + slot);
                const float *reg, *anc;
                int local, cnt;
                if (n < N0)        { reg = reg0; anc = anc0; local = n;        cnt = N0; }
                else if (n < OFF2) { reg = reg1; anc = anc1; local = n - OFF1; cnt = N1; }
                else               { reg = reg2; anc = anc2; local = n - OFF2; cnt = N2; }
                size_t base = (size_t)b * cnt + local;

                float4 rg = __ldg(reinterpret_cast<const float4*>(reg + base * 4));
                const float* ap = anc + base * 5;
                float ax = __ldg(ap),     ay = __ldg(ap + 1);
                float aw = __ldg(ap + 2), ah = __ldg(ap + 3);
                float st = __ldg(ap + 4);

                float cx = __fmul_rn(__fadd_rn(sigm(rg.x), ax), st);
                float cy = __fmul_rn(__fadd_rn(sigm(rg.y), ay), st);
                float w  = __fdiv_rn(__fmul_rn(expf(rg.z), aw), st);
                float h  = __fdiv_rn(__fmul_rn(expf(rg.w), ah), st);
                float x1 = __fsub_rn(cx, __fmul_rn(0.5f, w));
                float y1 = __fsub_rn(cy, __fmul_rn(0.5f, h));
                float x2 = __fadd_rn(w, x1);
                float y2 = __fadd_rn(h, y1);

                cx1[tid] = max((int)x1, 0);
                cy1[tid] = max((int)y1, 0);
                cx2[tid] = min((int)x2, IMGMAX);
                cy2[tid] = min((int)y2, IMGMAX);
                cslot[tid] = (int)slot;
            }
            // limit: valid flags form a prefix (scores sorted desc)
            unsigned bal = __ballot_sync(0xffffffffu, valid);
            if ((tid & 31) == 0) limw[tid >> 5] = __popc(bal);
        }
        __syncthreads();
        if (tid == 0) {
            int lim = 0;
#pragma unroll
            for (int wq = 0; wq < CW; ++wq) lim += (int)limw[wq];
            s_limit = lim;
        }
        __syncthreads();
        int limit = s_limit;
        int kept0 = s_kept;

        // suppression vs boxes kept in earlier chunks
        if (tid < CH) {
            bool sup = false;
            if (tid < limit) {
                int x1 = cx1[tid], y1 = cy1[tid], x2 = cx2[tid], y2 = cy2[tid];
                int ar = (x2 - x1) * (y2 - y1);
                for (int k2 = 0; k2 < kept0; ++k2) {
                    int p1 = kp1[k2], p2 = kp2[k2];
                    int qx1 = p1 & 0xFFFF, qy1 = p1 >> 16;
                    int qx2 = p2 & 0xFFFF, qy2 = p2 >> 16;
                    int iw = min(x2, qx2) - max(x1, qx1);
                    int ih = min(y2, qy2) - max(y1, qy1);
                    if (iw > 0 && ih > 0) {
                        int inter = iw * ih;
                        if (3 * inter > ar + (qx2 - qx1) * (qy2 - qy1)) sup = true;
                    }
                }
            }
            unsigned bal = __ballot_sync(0xffffffffu, sup);
            if ((tid & 31) == 0) supv[tid >> 5] = bal;
        }
        __syncthreads();   // also: everyone done reading sort/stage smem

        // within-chunk suppression matrix: M[i][w] bit jj = (j = w*32+jj > i) suppressed-by-i
        for (int task = tid; task < CH * CW; task += 1024) {
            int w = task & (CW - 1);
            int i = task >> 4;
            unsigned bits = 0u;
            int jbase = w << 5;
            if (i < limit && jbase + 31 > i) {
                int x1 = cx1[i], y1 = cy1[i], x2 = cx2[i], y2 = cy2[i];
                int ar = (x2 - x1) * (y2 - y1);
                int jmax = min(jbase + 32, limit);
#pragma unroll 4
                for (int j = jbase; j < jmax; ++j) {
                    if (j > i) {
                        int iw = min(x2, cx2[j]) - max(x1, cx1[j]);
                        int ih = min(y2, cy2[j]) - max(y1, cy1[j]);
                        if (iw > 0 && ih > 0) {
                            int inter = iw * ih;
                            if (3 * inter > ar + (cx2[j] - cx1[j]) * (cy2[j] - cy1[j]))
                                bits |= (1u << (j - jbase));
                        }
                    }
                }
            }
            sh.M[i][w] = bits;
        }
        __syncthreads();

        // warp-0 bitmask DP: one iteration per KEPT box
        if (tid < 32) {
            int kept = kept0;
            unsigned alive = 0u;
            if (tid < CW) {
                int lo = tid << 5;
                unsigned vm = (limit <= lo) ? 0u
                            : ((limit >= lo + 32) ? 0xFFFFFFFFu : ((1u << (limit - lo)) - 1u));
                alive = vm & ~supv[tid];
            }
            while (kept < MAXDET) {
                int c = alive ? ((tid << 5) + __ffs(alive) - 1) : 0x7FFFFFFF;
#pragma unroll
                for (int o = 16; o; o >>= 1) c = min(c, __shfl_xor_sync(0xffffffffu, c, o));
                if (c == 0x7FFFFFFF) break;
                if (tid == 0) {
                    kp1[kept] = cx1[c] | (cy1[c] << 16);
                    kp2[kept] = cx2[c] | (cy2[c] << 16);
                    kslot[kept] = cslot[c];
                }
                kept++;
                unsigned supbits = (tid < CW) ? sh.M[c][tid] : 0u;
                alive &= ~supbits;
                if (tid == (c >> 5)) alive &= ~(1u << (c & 31));
                __syncwarp();
            }
            if (tid == 0) {
                s_kept = kept;
                s_done = (kept >= MAXDET) || (limit < CH);
            }
        }
        __syncthreads();
        if (s_done) break;
        __syncthreads();   // protect ckey/c-arrays/M before next chunk rewrites
    }

    // ---- outputs (parallel) ----
    int kept = s_kept;
    const int* gcls = g_cls + b * NTOT;
    for (int k = tid; k < MAXDET; k += 1024) {
        float osc = -1.0f, ocl = -1.0f, ox1 = -1.0f, oy1 = -1.0f, ox2 = -1.0f, oy2 = -1.0f;
        if (k < kept) {
            int slot = kslot[k];
            osc = __ldg(cs + slot);
            ocl = (float)__ldg(gcls + __ldg(cidx + slot));
            int p1 = kp1[k], p2 = kp2[k];
            ox1 = (float)(p1 & 0xFFFF); oy1 = (float)(p1 >> 16);
            ox2 = (float)(p2 & 0xFFFF); oy2 = (float)(p2 >> 16);
        }
        out[b * MAXDET + k] = osc;
        out[BATCH * MAXDET + b * MAXDET + k] = ocl;
        int ob = 2 * BATCH * MAXDET + (b * MAXDET + k) * 4;
        out[ob] = ox1; out[ob + 1] = oy1; out[ob + 2] = ox2; out[ob + 3] = oy2;
    }
}

// ---------------- launcher ----------------
extern "C" void kernel_launch(void* const* d_in, const int* in_sizes, int n_in,
                              void* d_out, int out_size)
{
    (void)out_size;
    static const int dictSizes[12] = {  8664,  34656,   693120,  43320,
                                       34656, 138624,  2772480, 173280,
                                      138624, 554496, 11089920, 693120 };
    static const int sigSizes[12]  = {  8664,  34656, 138624,
                                       34656, 138624, 554496,
                                      693120, 2772480, 11089920,
                                       43320, 173280, 693120 };
    bool isDict = (n_in >= 12), isSig = (n_in >= 12);
    for (int i = 0; i < 12 && i < n_in; i++) {
        if (in_sizes[i] != dictSizes[i]) isDict = false;
        if (in_sizes[i] != sigSizes[i])  isSig  = false;
    }

    // canonical: [0..2]=obj, [3..5]=reg, [6..8]=cls, [9..11]=anchors
    const float* in[12];
    if (isSig && !isDict) {
        for (int i = 0; i < 12; i++) in[i] = (const float*)d_in[i];
    } else {
        for (int l = 0; l < 3; l++) {
            in[l]     = (const float*)d_in[4 * l + 0];
            in[3 + l] = (const float*)d_in[4 * l + 1];
            in[6 + l] = (const float*)d_in[4 * l + 2];
            in[9 + l] = (const float*)d_in[4 * l + 3];
        }
    }

    int nthreads = BATCH * NTOT * 4;
    decode_kernel<<<(nthreads + 255) / 256, 256>>>(
        in[0], in[6], in[1], in[7], in[2], in[8]);

    dim3 g2(3, BATCH);
    topk_kernel<<<g2, TKT>>>();

    sortnms_kernel<<<BATCH, 1024>>>(in[3], in[9], in[4], in[10], in[5], in[11],
                                    (float*)d_out);
}

// round 5
// speedup vs baseline: 2.0141x; 2.0141x over previous
#include <cuda_runtime.h>
#include <math.h>

// ---------------- problem constants ----------------
#define NTOT   22743
#define N0     1083
#define N1     4332
#define N2     17328
#define OFF1   1083
#define OFF2   5415
#define BATCH  8
#define TOPK   1000
#define NCAND  3000
#define MAXDET 100
#define IMGMAX 607
#define SORTN  4096
#define CH     512          // NMS chunk size
#define CW     16           // CH/32

// ---------------- device scratch ----------------
__device__ float g_score[BATCH * NTOT];
__device__ int   g_cls[BATCH * NTOT];
__device__ float g_cscore[BATCH * NCAND];
__device__ int   g_cidx[BATCH * NCAND];     // anchor index n within image

__device__ __forceinline__ float sigm(float x) { return 1.0f / (1.0f + expf(-x)); }

// ---------------- stage 1: decode scores only (4 threads / anchor) ----------------
__global__ void decode_kernel(
    const float* __restrict__ obj0, const float* __restrict__ cls0,
    const float* __restrict__ obj1, const float* __restrict__ cls1,
    const float* __restrict__ obj2, const float* __restrict__ cls2)
{
    int t = blockIdx.x * blockDim.x + threadIdx.x;
    int a = t >> 2;
    int sub = t & 3;
    if (a >= BATCH * NTOT) a = BATCH * NTOT - 1;   // duplicates write identical data
    int b = a / NTOT;
    int n = a - b * NTOT;

    const float *obj, *cls;
    int local, cnt;
    if (n < N0)        { obj = obj0; cls = cls0; local = n;        cnt = N0; }
    else if (n < OFF2) { obj = obj1; cls = cls1; local = n - OFF1; cnt = N1; }
    else               { obj = obj2; cls = cls2; local = n - OFF2; cnt = N2; }

    size_t base = (size_t)b * cnt + local;

    const float4* cp4 = reinterpret_cast<const float4*>(cls + base * 80) + sub * 5;
    float4 v0 = __ldg(cp4);
    float4 v1 = __ldg(cp4 + 1);
    float4 v2 = __ldg(cp4 + 2);
    float4 v3 = __ldg(cp4 + 3);
    float4 v4 = __ldg(cp4 + 4);

    float best = v0.x; int bi = 0;
    if (v0.y > best) { best = v0.y; bi = 1; }
    if (v0.z > best) { best = v0.z; bi = 2; }
    if (v0.w > best) { best = v0.w; bi = 3; }
    if (v1.x > best) { best = v1.x; bi = 4; }
    if (v1.y > best) { best = v1.y; bi = 5; }
    if (v1.z > best) { best = v1.z; bi = 6; }
    if (v1.w > best) { best = v1.w; bi = 7; }
    if (v2.x > best) { best = v2.x; bi = 8; }
    if (v2.y > best) { best = v2.y; bi = 9; }
    if (v2.z > best) { best = v2.z; bi = 10; }
    if (v2.w > best) { best = v2.w; bi = 11; }
    if (v3.x > best) { best = v3.x; bi = 12; }
    if (v3.y > best) { best = v3.y; bi = 13; }
    if (v3.z > best) { best = v3.z; bi = 14; }
    if (v3.w > best) { best = v3.w; bi = 15; }
    if (v4.x > best) { best = v4.x; bi = 16; }
    if (v4.y > best) { best = v4.y; bi = 17; }
    if (v4.z > best) { best = v4.z; bi = 18; }
    if (v4.w > best) { best = v4.w; bi = 19; }
    bi += sub * 20;

    // combine across the 4 sub-lanes; tie -> lower class index (first occurrence)
#pragma unroll
    for (int off = 1; off <= 2; off <<= 1) {
        float ov = __shfl_xor_sync(0xffffffffu, best, off);
        int   oi = __shfl_xor_sync(0xffffffffu, bi, off);
        if (ov > best || (ov == best && oi < bi)) { best = ov; bi = oi; }
    }

    if (sub == 0) {
        float o = sigm(__ldg(obj + base));
        g_score[a] = sigm(best) * o;
        g_cls[a]   = bi;
    }
}

// ---------------- stage 2: radix-256 exact top-1000 ----------------
#define TKT 512
#define PER 34   // ceil(17328/512)

__global__ void __launch_bounds__(TKT) topk_kernel()
{
    int level = blockIdx.x, b = blockIdx.y;
    int offs = (level == 0) ? 0  : ((level == 1) ? OFF1 : OFF2);
    int cnt  = (level == 0) ? N0 : ((level == 1) ? N1  : N2);
    const unsigned* sc = reinterpret_cast<const unsigned*>(g_score + b * NTOT + offs);

    int tid = threadIdx.x;
    int lane = tid & 31, warp = tid >> 5;

    unsigned v[PER];
#pragma unroll
    for (int k = 0; k < PER; ++k) {
        int i = tid + (k << 9);
        v[k] = (i < cnt) ? __ldg(sc + i) : 0u;
    }

    __shared__ unsigned hist[256];
    __shared__ unsigned s_prefix;
    __shared__ int s_need;
    __shared__ unsigned wred[16];
    __shared__ int s_found;

    // 4 rounds of radix-256 selection on score bits (all >= 0): find exact
    // tau = bits of the TOPK-th largest, and count strictly greater.
    unsigned prefix = 0;
    int need = TOPK;
#pragma unroll
    for (int s = 24; s >= 0; s -= 8) {
        for (int h = tid; h < 256; h += TKT) hist[h] = 0;
        __syncthreads();
        unsigned himask = (s == 24) ? 0u : (0xFFFFFFFFu << (s + 8));
#pragma unroll
        for (int k = 0; k < PER; ++k) {
            int i = tid + (k << 9);
            if (i < cnt && ((v[k] ^ prefix) & himask) == 0)
                atomicAdd(&hist[(v[k] >> s) & 255], 1u);
        }
        __syncthreads();
        // suffix-inclusive scan: hist[b] := sum_{b'=b..255} hist[b']
        for (int d = 1; d < 256; d <<= 1) {
            unsigned add = 0;
            if (tid < 256) add = (tid + d < 256) ? hist[tid + d] : 0u;
            __syncthreads();
            if (tid < 256) hist[tid] += add;
            __syncthreads();
        }
        if (tid < 256) {
            unsigned Sb  = hist[tid];
            unsigned Sb1 = (tid < 255) ? hist[tid + 1] : 0u;
            if (Sb >= (unsigned)need && Sb1 < (unsigned)need) {   // unique crossing bin
                s_prefix = prefix | ((unsigned)tid << s);
                s_need   = need - (int)Sb1;
            }
        }
        __syncthreads();
        prefix = s_prefix;
        need   = s_need;
        __syncthreads();
    }
    unsigned tau = prefix;
    unsigned mtot = (unsigned)(TOPK - need);

    // exclusive scan of per-thread strictly-greater counts
    unsigned c = 0;
#pragma unroll
    for (int k = 0; k < PER; ++k) c += (v[k] > tau) ? 1u : 0u;
    unsigned ws = c;
#pragma unroll
    for (int o = 1; o < 32; o <<= 1) {
        unsigned nb = __shfl_up_sync(0xffffffffu, ws, o);
        if (lane >= o) ws += nb;
    }
    if (lane == 31) wred[warp] = ws;
    __syncthreads();
    if (tid < 32) {
        unsigned s2 = (tid < 16) ? wred[tid] : 0u;
#pragma unroll
        for (int o = 1; o < 16; o <<= 1) {
            unsigned nb = __shfl_up_sync(0xffffffffu, s2, o);
            if (lane >= o) s2 += nb;
        }
        if (tid < 16) wred[tid] = s2;
    }
    __syncthreads();
    unsigned excl = ws - c + (warp ? wred[warp - 1] : 0u);

    unsigned pos = excl;
#pragma unroll
    for (int k = 0; k < PER; ++k) {
        int i = tid + (k << 9);
        if (i < cnt && v[k] > tau) {
            int s2 = b * NCAND + level * TOPK + (int)pos;
            g_cscore[s2] = __uint_as_float(v[k]);
            g_cidx[s2]   = offs + i;
            pos++;
        }
    }
    __syncthreads();

    // fill remaining 'need' slots with == tau entries, ascending index
    int last = -1;
    for (int rep = 0; rep < need; ++rep) {
        unsigned lm = 0xFFFFFFFFu;
#pragma unroll
        for (int k = 0; k < PER; ++k) {
            int i = tid + (k << 9);
            if (i < cnt && i > last && v[k] == tau) lm = min(lm, (unsigned)i);
        }
#pragma unroll
        for (int o = 16; o; o >>= 1) lm = min(lm, __shfl_down_sync(0xffffffffu, lm, o));
        if (lane == 0) wred[warp] = lm;
        __syncthreads();
        if (tid < 32) {
            unsigned s2 = (tid < 16) ? wred[tid] : 0xFFFFFFFFu;
#pragma unroll
            for (int o = 8; o; o >>= 1) s2 = min(s2, __shfl_down_sync(0xffffffffu, s2, o));
            if (tid == 0) s_found = (int)s2;
        }
        __syncthreads();
        int found = s_found;
        if (tid == 0 && found >= 0 && found < cnt) {
            int s2 = b * NCAND + level * TOPK + (int)mtot + rep;
            g_cscore[s2] = __uint_as_float(tau);
            g_cidx[s2]   = offs + found;
        }
        last = found;
        __syncthreads();
    }
}

// ---------------- stage 3: fused bitonic sort + chunked bitmask NMS ----------------
__device__ __forceinline__ unsigned long long u64max(unsigned long long a, unsigned long long b) { return a > b ? a : b; }
__device__ __forceinline__ unsigned long long u64min(unsigned long long a, unsigned long long b) { return a < b ? a : b; }
__device__ __forceinline__ void cswap(unsigned long long& a, unsigned long long& b, bool desc)
{
    if (desc ? (a < b) : (a > b)) { unsigned long long t = a; a = b; b = t; }
}

__global__ void __launch_bounds__(1024) sortnms_kernel(
    const float* __restrict__ reg0, const float* __restrict__ anc0,
    const float* __restrict__ reg1, const float* __restrict__ anc1,
    const float* __restrict__ reg2, const float* __restrict__ anc2,
    float* __restrict__ out)
{
    int b = blockIdx.x;
    int tid = threadIdx.x;
    int i0 = tid << 2;

    __shared__ union ShMem {
        unsigned long long sk[SORTN];     // sort workspace
        unsigned M[CH][CW];               // NMS suppression matrix (same bytes)
    } sh;
    __shared__ unsigned long long ckey[CH];
    __shared__ int cx1[CH], cy1[CH], cx2[CH], cy2[CH], cslot[CH];
    __shared__ unsigned supv[CW];
    __shared__ unsigned limw[CW];
    __shared__ int kp1[MAXDET], kp2[MAXDET], kslot[MAXDET];
    __shared__ int s_kept, s_done;
    __shared__ int s_limit;

    if (tid == 0) { s_kept = 0; s_done = 0; }

    // ---- build keys: score bits << 32 | ~slot (desc score, asc slot on ties) ----
    const float* cs = g_cscore + b * NCAND;
    unsigned long long r[4];
#pragma unroll
    for (int s = 0; s < 4; ++s) {
        int i = i0 + s;
        r[s] = (i < NCAND)
             ? (((unsigned long long)__float_as_uint(__ldg(cs + i)) << 32)
                | (unsigned long long)(0xFFFFFFFFu - (unsigned)i))
             : 0ull;
    }
    __syncthreads();

    // ---- bitonic sort (descending), 4 elems/thread ----
    for (int k = 2; k <= SORTN; k <<= 1) {
        for (int j = k >> 1; j > 0; j >>= 1) {
            if (j >= 128) {
                sh.sk[i0] = r[0]; sh.sk[i0 + 1] = r[1]; sh.sk[i0 + 2] = r[2]; sh.sk[i0 + 3] = r[3];
                __syncthreads();
                int pb = i0 ^ j;
                bool takeMax = (((i0 & k) == 0) != ((i0 & j) != 0));
#pragma unroll
                for (int s = 0; s < 4; ++s) {
                    unsigned long long p = sh.sk[pb + s];
                    r[s] = takeMax ? u64max(r[s], p) : u64min(r[s], p);
                }
                __syncthreads();
            } else if (j >= 4) {
                int lx = j >> 2;
                bool takeMax = (((i0 & k) == 0) != ((i0 & j) != 0));
#pragma unroll
                for (int s = 0; s < 4; ++s) {
                    unsigned long long p = __shfl_xor_sync(0xffffffffu, r[s], lx);
                    r[s] = takeMax ? u64max(r[s], p) : u64min(r[s], p);
                }
            } else if (j == 2) {
                cswap(r[0], r[2], ((i0    ) & k) == 0);
                cswap(r[1], r[3], ((i0 + 1) & k) == 0);
            } else {
                cswap(r[0], r[1], ((i0    ) & k) == 0);
                cswap(r[2], r[3], ((i0 + 2) & k) == 0);
            }
        }
    }

    const int* cidx = g_cidx + b * NCAND;

    // ---- chunked NMS ----
    for (int cb = 0; cb < NCAND; cb += CH) {
        // stage this chunk's sorted keys from registers into smem
#pragma unroll
        for (int s = 0; s < 4; ++s) {
            int rank = i0 + s;
            if (rank >= cb && rank < cb + CH) ckey[rank - cb] = r[s];
        }
        __syncthreads();

        // load + lazily decode boxes for valid candidates
        bool valid = false;
        if (tid < CH) {
            unsigned long long key = ckey[tid];
            float sc = __uint_as_float((unsigned)(key >> 32));
            unsigned slot = 0xFFFFFFFFu - (unsigned)key;
            valid = (sc > 0.05f);
            if (valid) {
                int n = __ldg(cidx + slot);
                const float *reg, *anc;
                int local, cnt;
                if (n < N0)        { reg = reg0; anc = anc0; local = n;        cnt = N0; }
                else if (n < OFF2) { reg = reg1; anc = anc1; local = n - OFF1; cnt = N1; }
                else               { reg = reg2; anc = anc2; local = n - OFF2; cnt = N2; }
                size_t base = (size_t)b * cnt + local;

                float4 rg = __ldg(reinterpret_cast<const float4*>(reg + base * 4));
                const float* ap = anc + base * 5;
                float ax = __ldg(ap),     ay = __ldg(ap + 1);
                float aw = __ldg(ap + 2), ah = __ldg(ap + 3);
                float st = __ldg(ap + 4);

                float cx = __fmul_rn(__fadd_rn(sigm(rg.x), ax), st);
                float cy = __fmul_rn(__fadd_rn(sigm(rg.y), ay), st);
                float w  = __fdiv_rn(__fmul_rn(expf(rg.z), aw), st);
                float h  = __fdiv_rn(__fmul_rn(expf(rg.w), ah), st);
                float x1 = __fsub_rn(cx, __fmul_rn(0.5f, w));
                float y1 = __fsub_rn(cy, __fmul_rn(0.5f, h));
                float x2 = __fadd_rn(w, x1);
                float y2 = __fadd_rn(h, y1);

                cx1[tid] = max((int)x1, 0);
                cy1[tid] = max((int)y1, 0);
                cx2[tid] = min((int)x2, IMGMAX);
                cy2[tid] = min((int)y2, IMGMAX);
                cslot[tid] = (int)slot;
            }
            unsigned bal = __ballot_sync(0xffffffffu, valid);
            if ((tid & 31) == 0) limw[tid >> 5] = __popc(bal);
        }
        __syncthreads();
        if (tid == 0) {
            int lim = 0;
#pragma unroll
            for (int wq = 0; wq < CW; ++wq) lim += (int)limw[wq];
            s_limit = lim;
        }
        __syncthreads();
        int limit = s_limit;
        int kept0 = s_kept;

        // suppression vs boxes kept in earlier chunks (k2 uniform -> broadcast)
        if (tid < CH) {
            bool sup = false;
            if (tid < limit) {
                int x1 = cx1[tid], y1 = cy1[tid], x2 = cx2[tid], y2 = cy2[tid];
                int ar = (x2 - x1) * (y2 - y1);
                for (int k2 = 0; k2 < kept0; ++k2) {
                    int p1 = kp1[k2], p2 = kp2[k2];
                    int qx1 = p1 & 0xFFFF, qy1 = p1 >> 16;
                    int qx2 = p2 & 0xFFFF, qy2 = p2 >> 16;
                    int iw = min(x2, qx2) - max(x1, qx1);
                    int ih = min(y2, qy2) - max(y1, qy1);
                    if (iw > 0 && ih > 0) {
                        int inter = iw * ih;
                        if (3 * inter > ar + (qx2 - qx1) * (qy2 - qy1)) sup = true;
                    }
                }
            }
            unsigned bal = __ballot_sync(0xffffffffu, sup);
            if ((tid & 31) == 0) supv[tid >> 5] = bal;
        }
        __syncthreads();

        // within-chunk suppression matrix.
        // MAPPING IS LOAD-BEARING: lanes take consecutive i (conflict-free per-i
        // loads), w uniform across the warp -> inner-loop j loads are BROADCAST.
        for (int task = tid; task < CH * CW; task += 1024) {
            int w = task >> 9;            // uniform across warp
            int i = task & (CH - 1);      // consecutive across lanes
            unsigned bits = 0u;
            int jbase = w << 5;
            if (i < limit && jbase + 31 > i) {
                int x1 = cx1[i], y1 = cy1[i], x2 = cx2[i], y2 = cy2[i];
                int ar = (x2 - x1) * (y2 - y1);
                int jmax = min(jbase + 32, limit);
#pragma unroll 4
                for (int j = jbase; j < jmax; ++j) {
                    if (j > i) {
                        int iw = min(x2, cx2[j]) - max(x1, cx1[j]);
                        int ih = min(y2, cy2[j]) - max(y1, cy1[j]);
                        if (iw > 0 && ih > 0) {
                            int inter = iw * ih;
                            if (3 * inter > ar + (cx2[j] - cx1[j]) * (cy2[j] - cy1[j]))
                                bits |= (1u << (j - jbase));
                        }
                    }
                }
            }
            sh.M[i][w] = bits;
        }
        __syncthreads();

        // warp-0 bitmask DP: one iteration per KEPT box
        if (tid < 32) {
            int kept = kept0;
            unsigned alive = 0u;
            if (tid < CW) {
                int lo = tid << 5;
                unsigned vm = (limit <= lo) ? 0u
                            : ((limit >= lo + 32) ? 0xFFFFFFFFu : ((1u << (limit - lo)) - 1u));
                alive = vm & ~supv[tid];
            }
            while (kept < MAXDET) {
                int c = alive ? ((tid << 5) + __ffs(alive) - 1) : 0x7FFFFFFF;
#pragma unroll
                for (int o = 16; o; o >>= 1) c = min(c, __shfl_xor_sync(0xffffffffu, c, o));
                if (c == 0x7FFFFFFF) break;
                if (tid == 0) {
                    kp1[kept] = cx1[c] | (cy1[c] << 16);
                    kp2[kept] = cx2[c] | (cy2[c] << 16);
                    kslot[kept] = cslot[c];
                }
                kept++;
                unsigned supbits = (tid < CW) ? sh.M[c][tid] : 0u;
                alive &= ~supbits;
                if (tid == (c >> 5)) alive &= ~(1u << (c & 31));
                __syncwarp();
            }
            if (tid == 0) {
                s_kept = kept;
                s_done = (kept >= MAXDET) || (limit < CH);
            }
        }
        __syncthreads();
        if (s_done) break;
        __syncthreads();
    }

    // ---- outputs (parallel) ----
    int kept = s_kept;
    const int* gcls = g_cls + b * NTOT;
    for (int k = tid; k < MAXDET; k += 1024) {
        float osc = -1.0f, ocl = -1.0f, ox1 = -1.0f, oy1 = -1.0f, ox2 = -1.0f, oy2 = -1.0f;
        if (k < kept) {
            int slot = kslot[k];
            osc = __ldg(cs + slot);
            ocl = (float)__ldg(gcls + __ldg(cidx + slot));
            int p1 = kp1[k], p2 = kp2[k];
            ox1 = (float)(p1 & 0xFFFF); oy1 = (float)(p1 >> 16);
            ox2 = (float)(p2 & 0xFFFF); oy2 = (float)(p2 >> 16);
        }
        out[b * MAXDET + k] = osc;
        out[BATCH * MAXDET + b * MAXDET + k] = ocl;
        int ob = 2 * BATCH * MAXDET + (b * MAXDET + k) * 4;
        out[ob] = ox1; out[ob + 1] = oy1; out[ob + 2] = ox2; out[ob + 3] = oy2;
    }
}

// ---------------- launcher ----------------
extern "C" void kernel_launch(void* const* d_in, const int* in_sizes, int n_in,
                              void* d_out, int out_size)
{
    (void)out_size;
    static const int dictSizes[12] = {  8664,  34656,   693120,  43320,
                                       34656, 138624,  2772480, 173280,
                                      138624, 554496, 11089920, 693120 };
    static const int sigSizes[12]  = {  8664,  34656, 138624,
                                       34656, 138624, 554496,
                                      693120, 2772480, 11089920,
                                       43320, 173280, 693120 };
    bool isDict = (n_in >= 12), isSig = (n_in >= 12);
    for (int i = 0; i < 12 && i < n_in; i++) {
        if (in_sizes[i] != dictSizes[i]) isDict = false;
        if (in_sizes[i] != sigSizes[i])  isSig  = false;
    }

    // canonical: [0..2]=obj, [3..5]=reg, [6..8]=cls, [9..11]=anchors
    const float* in[12];
    if (isSig && !isDict) {
        for (int i = 0; i < 12; i++) in[i] = (const float*)d_in[i];
    } else {
        for (int l = 0; l < 3; l++) {
            in[l]     = (const float*)d_in[4 * l + 0];
            in[3 + l] = (const float*)d_in[4 * l + 1];
            in[6 + l] = (const float*)d_in[4 * l + 2];
            in[9 + l] = (const float*)d_in[4 * l + 3];
        }
    }

    int nthreads = BATCH * NTOT * 4;
    decode_kernel<<<(nthreads + 255) / 256, 256>>>(
        in[0], in[6], in[1], in[7], in[2], in[8]);

    dim3 g2(3, BATCH);
    topk_kernel<<<g2, TKT>>>();

    sortnms_kernel<<<BATCH, 1024>>>(in[3], in[9], in[4], in[10], in[5], in[11],
                                    (float*)d_out);
}